// round 4
// baseline (speedup 1.0000x reference)
#include <cuda_runtime.h>
#include <cstdint>
#include <cfloat>

#define BB 8
#define NN 1024
#define KK 20
#define BN (BB*NN)
#define EPSV 1e-5f

typedef unsigned long long ull;

__device__ __forceinline__ ull pack2(float lo, float hi) {
    ull r; asm("mov.b64 %0, {%1,%2};" : "=l"(r) : "f"(lo), "f"(hi)); return r;
}
__device__ __forceinline__ void unpack2(ull v, float& lo, float& hi) {
    asm("mov.b64 {%0,%1}, %2;" : "=f"(lo), "=f"(hi) : "l"(v));
}
__device__ __forceinline__ ull ffma2(ull a, ull b, ull c) {
    ull d; asm("fma.rn.f32x2 %0, %1, %2, %3;" : "=l"(d) : "l"(a), "l"(b), "l"(c)); return d;
}

// ---------------- scratch (device globals; no runtime allocation) ----------------
__device__ float g_pair[(size_t)BB*NN*NN];   // 32MB pairwise affinities
__device__ float g_xt[BB*128*NN];            // transposed features (B, C, N), C<=128
__device__ float g_sq[BN];
__device__ int   g_idx[BN*KK];
__device__ float g_a[BN*512];                // W1 * x  per point  (B*N, O)
__device__ float g_d[BN*512];                // (W2-W1) * x per point
__device__ float g_ymax[BN*512];
__device__ float g_ymin[BN*512];
__device__ float g_ps1[BN*512];              // per-(b,n) partial sum of y over k
__device__ float g_ps2[BN*512];              // per-(b,n) partial sum of y^2 over k
__device__ float g_cat[BN*512];              // concatenated block outputs (B, N, 512)
__device__ float g_wta[512*512];             // W1^T   (C x O)
__device__ float g_wtd[512*512];             // (W2-W1)^T (C x O)
__device__ float g_cs1[16*512];
__device__ float g_cs2[16*512];
__device__ float g_stats[512*3];             // mean, scale(=g*rsqrt(v+eps)), beta
__device__ float g_bmax[BB*512];
__device__ float g_bmin[BB*512];
__device__ float g_bs1[BB*512];
__device__ float g_bs2[BB*512];
__device__ float g_feat[BB*512];

__device__ __forceinline__ const float* src_ptr(const float* ext, int coff) {
    return ext ? ext : (g_cat + coff);
}

// ---------------- weight transpose: wta[c*O+o] = W1[o][c], wtd = (W2-W1)^T ----------------
__global__ void k_prep_w(const float* __restrict__ w, int C, int O, int dual) {
    int i = blockIdx.x * 256 + threadIdx.x;
    if (i >= C * O) return;
    int c = i / O, o = i % O;
    if (dual) {
        float a = w[o * 2 * C + c];
        g_wta[c * O + o] = a;
        g_wtd[c * O + o] = w[o * 2 * C + C + c] - a;
    } else {
        g_wta[c * O + o] = w[o * C + c];
    }
}

// ---------------- feature transpose: g_xt[b][c][n] = src[(b*N+n)*ld + c] ----------------
__global__ void k_xt(const float* ext, int ldx, int coff, int C) {
    int i = blockIdx.x * 256 + threadIdx.x;
    if (i >= BB * C * NN) return;
    int n = i % NN;
    int c = (i / NN) % C;
    int b = i / (NN * C);
    const float* src = src_ptr(ext, coff);
    g_xt[(b * C + c) * NN + n] = src[(size_t)(b * NN + n) * ldx + c];
}

// ---------------- squared norms ----------------
__global__ void k_sq(const float* ext, int ldx, int coff, int C) {
    int r = blockIdx.x * 256 + threadIdx.x;
    if (r >= BN) return;
    const float* src = src_ptr(ext, coff) + (size_t)r * ldx;
    float s = 0.f;
    for (int c = 0; c < C; c++) { float v = src[c]; s += v * v; }
    g_sq[r] = s;
}

// ---------------- pairwise affinity (symmetric, f32x2):
// pair[b][n][m] = 2<x_n,x_m> - |x_n|^2 - |x_m|^2 ; only tn<=tm tiles computed ----------------
__global__ __launch_bounds__(256) void k_pair(int C) {
    __shared__ float As2[16][132];   // duplicated n-side operand
    __shared__ float Bs[16][68];
    int b = blockIdx.z;
    // decode triangular tile pair (tn <= tm) from blockIdx.x in [0,136)
    int t = blockIdx.x;
    int tn = 0;
    while (t >= 16 - tn) { t -= 16 - tn; tn++; }
    int tm = tn + t;
    int n0 = tn * 64, m0 = tm * 64;
    const float* xt = g_xt + (size_t)b * C * NN;
    int tid = threadIdx.x;
    int ty = tid >> 4, tx = tid & 15;

    ull acc[4][2];
#pragma unroll
    for (int i = 0; i < 4; i++) { acc[i][0] = 0ull; acc[i][1] = 0ull; }

    for (int c0 = 0; c0 < C; c0 += 16) {
#pragma unroll
        for (int r2 = 0; r2 < 4; r2++) {
            int li = tid + 256 * r2;
            int i = li & 63, k = li >> 6;
            float va = 0.f, vb = 0.f;
            if (c0 + k < C) {
                va = xt[(c0 + k) * NN + n0 + i];
                vb = xt[(c0 + k) * NN + m0 + i];
            }
            *(float2*)&As2[k][2 * i] = make_float2(va, va);
            Bs[k][i] = vb;
        }
        __syncthreads();
#pragma unroll
        for (int k = 0; k < 16; k++) {
            float4 a01 = *(const float4*)&As2[k][ty * 8];
            float4 a23 = *(const float4*)&As2[k][ty * 8 + 4];
            float4 bv  = *(const float4*)&Bs[k][tx * 4];
            ull ad[4] = { pack2(a01.x, a01.y), pack2(a01.z, a01.w),
                          pack2(a23.x, a23.y), pack2(a23.z, a23.w) };
            ull bp[2] = { pack2(bv.x, bv.y), pack2(bv.z, bv.w) };
#pragma unroll
            for (int i = 0; i < 4; i++)
#pragma unroll
                for (int j = 0; j < 2; j++)
                    acc[i][j] = ffma2(ad[i], bp[j], acc[i][j]);
        }
        __syncthreads();
    }
    float sqm[4];
#pragma unroll
    for (int j = 0; j < 4; j++) sqm[j] = g_sq[b * NN + m0 + tx * 4 + j];

    float vals[4][4];
#pragma unroll
    for (int i = 0; i < 4; i++) {
        float sqn = g_sq[b * NN + n0 + ty * 4 + i];
        float v0, v1, v2, v3;
        unpack2(acc[i][0], v0, v1);
        unpack2(acc[i][1], v2, v3);
        vals[i][0] = 2.f * v0 - sqn - sqm[0];
        vals[i][1] = 2.f * v1 - sqn - sqm[1];
        vals[i][2] = 2.f * v2 - sqn - sqm[2];
        vals[i][3] = 2.f * v3 - sqn - sqm[3];
    }
    // normal tile (coalesced float4)
#pragma unroll
    for (int i = 0; i < 4; i++) {
        int n = n0 + ty * 4 + i;
        float4 v = make_float4(vals[i][0], vals[i][1], vals[i][2], vals[i][3]);
        *(float4*)&g_pair[(size_t)b * NN * NN + (size_t)n * NN + m0 + tx * 4] = v;
    }
    // mirror tile (scattered, only off-diagonal)
    if (tn != tm) {
        float* base = g_pair + (size_t)b * NN * NN;
#pragma unroll
        for (int j = 0; j < 4; j++) {
            int m = m0 + tx * 4 + j;
#pragma unroll
            for (int i = 0; i < 4; i++)
                base[(size_t)m * NN + n0 + ty * 4 + i] = vals[i][j];
        }
    }
}

// ---------------- top-K: warp per row; lane-local sorted top-20, then 20 warp-argmax rounds ----------------
__global__ __launch_bounds__(256) void k_topk() {
    __shared__ float sv[8][32][21];
    __shared__ int   si[8][32][21];
    int warp = threadIdx.x >> 5, lane = threadIdx.x & 31;
    int r = blockIdx.x * 8 + warp;
    int b = r >> 10, n = r & 1023;
    const float* row = g_pair + (size_t)b * NN * NN + (size_t)n * NN;

    float* v = sv[warp][lane];
    int* ii = si[warp][lane];
#pragma unroll
    for (int t = 0; t < KK; t++) { v[t] = -FLT_MAX; ii[t] = 1 << 30; }

    for (int j = lane; j < NN; j += 32) {
        float p = row[j];
        if (p > v[KK - 1]) {                       // strict: equal keeps earlier (lower) index
            int pos = KK - 1;
            while (pos > 0 && v[pos - 1] < p) {    // strict: stable among ties
                v[pos] = v[pos - 1]; ii[pos] = ii[pos - 1]; pos--;
            }
            v[pos] = p; ii[pos] = j;
        }
    }
    __syncwarp();

    int ptr = 0;
    for (int t = 0; t < KK; t++) {
        float hv = (ptr < KK) ? v[ptr] : -FLT_MAX;
        int   hi = (ptr < KK) ? ii[ptr] : (1 << 30);
        float bv = hv; int bi = hi;
#pragma unroll
        for (int off = 16; off; off >>= 1) {
            float ov = __shfl_xor_sync(0xffffffffu, bv, off);
            int   oi = __shfl_xor_sync(0xffffffffu, bi, off);
            if (ov > bv || (ov == bv && oi < bi)) { bv = ov; bi = oi; }
        }
        if (hi == bi) ptr++;                       // winner lane (indices unique) advances
        if (lane == 0) g_idx[r * KK + t] = bi;
    }
}

// ---------------- tiled SGEMM (f32x2): A = X @ Wt (and D = X @ Wtd) ----------------
template <bool DUAL>
__global__ __launch_bounds__(256) void k_gemm(const float* ext, int ldx, int coff, int C, int O) {
    __shared__ float Xs2[16][132];   // duplicated row-side operand
    __shared__ float Wa[16][68];
    __shared__ float Wd[16][68];
    const float* X = src_ptr(ext, coff);
    int o0 = blockIdx.x * 64;
    int m0 = blockIdx.y * 64;
    int tid = threadIdx.x;
    int ty = tid >> 4, tx = tid & 15;

    ull acc[4][2], accd[4][2];
#pragma unroll
    for (int i = 0; i < 4; i++) {
        acc[i][0] = 0ull; acc[i][1] = 0ull;
        accd[i][0] = 0ull; accd[i][1] = 0ull;
    }

    for (int c0 = 0; c0 < C; c0 += 16) {
#pragma unroll
        for (int r2 = 0; r2 < 4; r2++) {
            int k = tid & 15;
            int i = (tid >> 4) + 16 * r2;
            float xv = 0.f;
            if (c0 + k < C) xv = X[(size_t)(m0 + i) * ldx + c0 + k];
            *(float2*)&Xs2[k][2 * i] = make_float2(xv, xv);
        }
#pragma unroll
        for (int r2 = 0; r2 < 4; r2++) {
            int li = tid + 256 * r2;
            int o = li & 63, k = li >> 6;
            float va = 0.f, vd = 0.f;
            if (c0 + k < C) {
                va = g_wta[(c0 + k) * O + o0 + o];
                if (DUAL) vd = g_wtd[(c0 + k) * O + o0 + o];
            }
            Wa[k][o] = va;
            if (DUAL) Wd[k][o] = vd;
        }
        __syncthreads();
#pragma unroll
        for (int k = 0; k < 16; k++) {
            float4 a01 = *(const float4*)&Xs2[k][ty * 8];
            float4 a23 = *(const float4*)&Xs2[k][ty * 8 + 4];
            float4 wv  = *(const float4*)&Wa[k][tx * 4];
            ull ad[4] = { pack2(a01.x, a01.y), pack2(a01.z, a01.w),
                          pack2(a23.x, a23.y), pack2(a23.z, a23.w) };
            ull wp[2] = { pack2(wv.x, wv.y), pack2(wv.z, wv.w) };
            ull dp[2];
            if (DUAL) {
                float4 dv = *(const float4*)&Wd[k][tx * 4];
                dp[0] = pack2(dv.x, dv.y); dp[1] = pack2(dv.z, dv.w);
            }
#pragma unroll
            for (int i = 0; i < 4; i++)
#pragma unroll
                for (int j = 0; j < 2; j++) {
                    acc[i][j] = ffma2(ad[i], wp[j], acc[i][j]);
                    if (DUAL) accd[i][j] = ffma2(ad[i], dp[j], accd[i][j]);
                }
        }
        __syncthreads();
    }
#pragma unroll
    for (int i = 0; i < 4; i++) {
        int m = m0 + ty * 4 + i;
        float4 va, vd;
        unpack2(acc[i][0], va.x, va.y);
        unpack2(acc[i][1], va.z, va.w);
        *(float4*)&g_a[(size_t)m * O + o0 + tx * 4] = va;
        if (DUAL) {
            unpack2(accd[i][0], vd.x, vd.y);
            unpack2(accd[i][1], vd.z, vd.w);
            *(float4*)&g_d[(size_t)m * O + o0 + tx * 4] = vd;
        }
    }
}

// ---------------- gather + per-(b,n) max/min over k + partial channel sums ----------------
__global__ void k_gather(int O) {
    int r = blockIdx.x;
    int b = r >> 10;
    __shared__ int sidx[KK];
    if (threadIdx.x < KK) sidx[threadIdx.x] = g_idx[r * KK + threadIdx.x];
    __syncthreads();
    int o = threadIdx.x;
    float dv = g_d[(size_t)r * O + o];
    float ymx = -FLT_MAX, ymn = FLT_MAX, s1 = 0.f, s2 = 0.f;
#pragma unroll
    for (int k = 0; k < KK; k++) {
        float y = g_a[(size_t)(b * NN + sidx[k]) * O + o] + dv;
        ymx = fmaxf(ymx, y);
        ymn = fminf(ymn, y);
        s1 += y;
        s2 += y * y;
    }
    g_ymax[(size_t)r * O + o] = ymx;
    g_ymin[(size_t)r * O + o] = ymn;
    g_ps1[(size_t)r * O + o] = s1;
    g_ps2[(size_t)r * O + o] = s2;
}

// ---------------- deterministic channel-stat reduction (2 levels) ----------------
__global__ void k_stat1(int O) {
    int ox = threadIdx.x & 31;
    int wy = threadIdx.x >> 5;
    int o = blockIdx.x * 32 + ox;
    int ci = blockIdx.y;
    const int CH = BN / 16;
    float s1 = 0.f, s2 = 0.f;
    int r0 = ci * CH;
    for (int r = r0 + wy; r < r0 + CH; r += 8) {
        s1 += g_ps1[(size_t)r * O + o];
        s2 += g_ps2[(size_t)r * O + o];
    }
    __shared__ float sh1[8][32], sh2[8][32];
    sh1[wy][ox] = s1; sh2[wy][ox] = s2;
    __syncthreads();
    if (wy == 0) {
        for (int w = 1; w < 8; w++) { s1 += sh1[w][ox]; s2 += sh2[w][ox]; }
        g_cs1[ci * O + o] = s1;
        g_cs2[ci * O + o] = s2;
    }
}

__global__ void k_stat2(int O, const float* __restrict__ g, const float* __restrict__ be, float invcnt) {
    int o = blockIdx.x * 256 + threadIdx.x;
    if (o >= O) return;
    float s1 = 0.f, s2 = 0.f;
    for (int ci = 0; ci < 16; ci++) { s1 += g_cs1[ci * O + o]; s2 += g_cs2[ci * O + o]; }
    float m = s1 * invcnt;
    float v = s2 * invcnt - m * m;
    float sc = g[o] * rsqrtf(v + EPSV);
    g_stats[o * 3 + 0] = m;
    g_stats[o * 3 + 1] = sc;
    g_stats[o * 3 + 2] = be[o];
}

// ---------------- finalize a block: pick max/min by sign(scale), BN affine, lrelu ----------------
__global__ void k_final(int O, int coff) {
    int r = blockIdx.x;
    int o = threadIdx.x;
    float m = g_stats[o * 3 + 0];
    float sc = g_stats[o * 3 + 1];
    float be = g_stats[o * 3 + 2];
    float y = (sc >= 0.f) ? g_ymax[(size_t)r * O + o] : g_ymin[(size_t)r * O + o];
    float t = (y - m) * sc + be;
    g_cat[(size_t)r * 512 + coff + o] = (t >= 0.f) ? t : 0.2f * t;
}

// ---------------- final stage: per-(b,o) max/min over N + channel sums ----------------
__global__ void k_fred() {
    int ox = threadIdx.x & 31;
    int wy = threadIdx.x >> 5;
    int o = blockIdx.x * 32 + ox;
    int b = blockIdx.y;
    float mx = -FLT_MAX, mn = FLT_MAX, s1 = 0.f, s2 = 0.f;
    for (int n = wy; n < NN; n += 8) {
        float v = g_a[(size_t)(b * NN + n) * 512 + o];
        mx = fmaxf(mx, v);
        mn = fminf(mn, v);
        s1 += v;
        s2 += v * v;
    }
    __shared__ float smx[8][32], smn[8][32], ss1[8][32], ss2[8][32];
    smx[wy][ox] = mx; smn[wy][ox] = mn; ss1[wy][ox] = s1; ss2[wy][ox] = s2;
    __syncthreads();
    if (wy == 0) {
        for (int w = 1; w < 8; w++) {
            mx = fmaxf(mx, smx[w][ox]);
            mn = fminf(mn, smn[w][ox]);
            s1 += ss1[w][ox];
            s2 += ss2[w][ox];
        }
        g_bmax[b * 512 + o] = mx;
        g_bmin[b * 512 + o] = mn;
        g_bs1[b * 512 + o] = s1;
        g_bs2[b * 512 + o] = s2;
    }
}

__global__ void k_feat(const float* __restrict__ g5, const float* __restrict__ b5) {
    int o = blockIdx.x * 256 + threadIdx.x;
    if (o >= 512) return;
    float s1 = 0.f, s2 = 0.f;
    for (int b = 0; b < BB; b++) { s1 += g_bs1[b * 512 + o]; s2 += g_bs2[b * 512 + o]; }
    float m = s1 / 8192.f;
    float v = s2 / 8192.f - m * m;
    float sc = g5[o] * rsqrtf(v + EPSV);
    float be = b5[o];
    for (int b = 0; b < BB; b++) {
        float y = (sc >= 0.f) ? g_bmax[b * 512 + o] : g_bmin[b * 512 + o];
        float t = (y - m) * sc + be;
        g_feat[b * 512 + o] = (t >= 0.f) ? t : 0.2f * t;
    }
}

__global__ void k_out(const float* __restrict__ wemb, float* __restrict__ out) {
    int b = blockIdx.x;
    int f = threadIdx.x;  // 256
    __shared__ float fr[512];
    for (int i = threadIdx.x; i < 512; i += 256) fr[i] = g_feat[b * 512 + i];
    __syncthreads();
    float acc = 0.f;
    for (int o = 0; o < 512; o++) acc += fr[o] * wemb[f * 512 + o];
    out[b * 256 + f] = acc;
}

// ---------------- host orchestration ----------------
static void run_stage(const float* xext, int ldx, int coff, int C, int O,
                      const float* w, const float* g, const float* bb, int outcoff) {
    k_prep_w<<<(C * O + 255) / 256, 256>>>(w, C, O, 1);
    k_xt<<<(BB * C * NN + 255) / 256, 256>>>(xext, ldx, coff, C);
    k_sq<<<BN / 256, 256>>>(xext, ldx, coff, C);
    k_pair<<<dim3(136, 1, BB), 256>>>(C);
    k_topk<<<BN / 8, 256>>>();
    k_gemm<true><<<dim3(O / 64, BN / 64), 256>>>(xext, ldx, coff, C, O);
    k_gather<<<BN, O>>>(O);
    k_stat1<<<dim3(O / 32, 16), 256>>>(O);
    k_stat2<<<(O + 255) / 256, 256>>>(O, g, bb, 1.0f / (float)(BN * KK));
    k_final<<<BN, O>>>(O, outcoff);
}

extern "C" void kernel_launch(void* const* d_in, const int* in_sizes, int n_in,
                              void* d_out, int out_size) {
    const float* x    = (const float*)d_in[0];
    const float* w1   = (const float*)d_in[1];
    const float* g1   = (const float*)d_in[2];
    const float* b1   = (const float*)d_in[3];
    const float* w2   = (const float*)d_in[4];
    const float* g2   = (const float*)d_in[5];
    const float* b2   = (const float*)d_in[6];
    const float* w3   = (const float*)d_in[7];
    const float* g3   = (const float*)d_in[8];
    const float* b3   = (const float*)d_in[9];
    const float* w4   = (const float*)d_in[10];
    const float* g4   = (const float*)d_in[11];
    const float* b4   = (const float*)d_in[12];
    const float* w5   = (const float*)d_in[13];
    const float* g5   = (const float*)d_in[14];
    const float* b5   = (const float*)d_in[15];
    const float* wemb = (const float*)d_in[16];
    float* out = (float*)d_out;

    // edge blocks: input (ptr, ld, coff, C) -> output channels at outcoff in g_cat
    run_stage(x,       3,   0,   3,   64, w1, g1, b1,   0);
    run_stage(nullptr, 512, 0,   64,  64, w2, g2, b2,  64);
    run_stage(nullptr, 512, 64,  64, 128, w3, g3, b3, 128);
    run_stage(nullptr, 512, 128, 128, 256, w4, g4, b4, 256);

    // final: y5 = cat @ w5^T  (512x512), stats over (b,n), per-b max over n, lrelu, @ wemb^T
    k_prep_w<<<(512 * 512 + 255) / 256, 256>>>(w5, 512, 512, 0);
    k_gemm<false><<<dim3(512 / 64, BN / 64), 256>>>(nullptr, 512, 0, 512, 512);
    k_fred<<<dim3(512 / 32, BB), 256>>>();
    k_feat<<<2, 256>>>(g5, b5);
    k_out<<<BB, 256>>>(wemb, out);
}

// round 6
// speedup vs baseline: 1.1064x; 1.1064x over previous
#include <cuda_runtime.h>
#include <cstdint>
#include <cfloat>

#define BB 8
#define NN 1024
#define KK 20
#define BN (BB*NN)
#define EPSV 1e-5f

// ---------------- scratch (device globals; no runtime allocation) ----------------
__device__ float g_pair[(size_t)BB*NN*NN];   // 32MB pairwise affinities
__device__ float g_xt[BB*128*NN];            // transposed features (B, C, N), C<=128
__device__ float g_sq[BN];
__device__ int   g_idx[BN*KK];
__device__ float g_ad[BN*512];               // [a | d] per point, width Ow (<=512)
__device__ float g_ymax[BN*256];
__device__ float g_ymin[BN*256];
__device__ float g_ps1[BN*256];              // per-(b,n) partial sum of y over k
__device__ float g_ps2[BN*256];              // per-(b,n) partial sum of y^2 over k
__device__ float g_cat[BN*512];              // concatenated block outputs (B, N, 512)
__device__ float g_wta[512*512];             // [W1 | (W2-W1)]^T : (C x Nw)
__device__ float g_cs1[16*512];
__device__ float g_cs2[16*512];
__device__ float g_stats[512*3];             // mean, scale(=g*rsqrt(v+eps)), beta
__device__ float g_bmax[BB*512];
__device__ float g_bmin[BB*512];
__device__ float g_bs1[BB*512];
__device__ float g_bs2[BB*512];
__device__ float g_feat[BB*512];

__device__ __forceinline__ const float* src_ptr(const float* ext, int coff) {
    return ext ? ext : (g_cat + coff);
}

// ---------------- weight prep: g_wta (C x 2O) = [W1^T | (W2-W1)^T] (dual) or W^T ----------------
__global__ void k_prep_w(const float* __restrict__ w, int C, int O, int dual) {
    int i = blockIdx.x * 256 + threadIdx.x;
    if (i >= C * O) return;
    int c = i / O, o = i % O;
    if (dual) {
        int Nw = 2 * O;
        float a = w[o * 2 * C + c];
        g_wta[c * Nw + o] = a;
        g_wta[c * Nw + O + o] = w[o * 2 * C + C + c] - a;
    } else {
        g_wta[c * O + o] = w[o * C + c];
    }
}

// ---------------- feature transpose: g_xt[b][c][n] = src[(b*N+n)*ld + c] ----------------
__global__ void k_xt(const float* ext, int ldx, int coff, int C) {
    int i = blockIdx.x * 256 + threadIdx.x;
    if (i >= BB * C * NN) return;
    int n = i % NN;
    int c = (i / NN) % C;
    int b = i / (NN * C);
    const float* src = src_ptr(ext, coff);
    g_xt[(b * C + c) * NN + n] = src[(size_t)(b * NN + n) * ldx + c];
}

// ---------------- squared norms ----------------
__global__ void k_sq(const float* ext, int ldx, int coff, int C) {
    int r = blockIdx.x * 256 + threadIdx.x;
    if (r >= BN) return;
    const float* src = src_ptr(ext, coff) + (size_t)r * ldx;
    float s = 0.f;
    for (int c = 0; c < C; c++) { float v = src[c]; s += v * v; }
    g_sq[r] = s;
}

// ---------------- pairwise affinity, 128x128 tiles, 8x8/thread, symmetric ----------------
// pair[b][n][m] = 2<x_n,x_m> - |x_n|^2 - |x_m|^2 ; only tn<=tm tiles computed, mirrored.
__global__ __launch_bounds__(256) void k_pair(int C) {
    __shared__ float As[8][132];
    __shared__ float Bs[8][132];
    int b = blockIdx.z;
    int t = blockIdx.x;                       // triangular tile id in [0,36)
    int tn = 0;
    while (t >= 8 - tn) { t -= 8 - tn; tn++; }
    int tm = tn + t;
    int n0 = tn * 128, m0 = tm * 128;
    const float* xt = g_xt + (size_t)b * C * NN;
    int tid = threadIdx.x;
    int tx = tid & 15, ty = tid >> 4;
    int lk = tid >> 5, ln4 = (tid & 31) * 4;

    float acc[8][8];
#pragma unroll
    for (int i = 0; i < 8; i++)
#pragma unroll
        for (int j = 0; j < 8; j++) acc[i][j] = 0.f;

    for (int c0 = 0; c0 < C; c0 += 8) {
        float4 va = make_float4(0.f, 0.f, 0.f, 0.f), vb = va;
        if (c0 + lk < C) {
            va = *(const float4*)&xt[(c0 + lk) * NN + n0 + ln4];
            vb = *(const float4*)&xt[(c0 + lk) * NN + m0 + ln4];
        }
        *(float4*)&As[lk][ln4] = va;
        *(float4*)&Bs[lk][ln4] = vb;
        __syncthreads();
#pragma unroll
        for (int k = 0; k < 8; k++) {
            float4 a0 = *(const float4*)&As[k][ty * 4];
            float4 a1 = *(const float4*)&As[k][64 + ty * 4];
            float4 b0 = *(const float4*)&Bs[k][tx * 4];
            float4 b1 = *(const float4*)&Bs[k][64 + tx * 4];
            float ar[8] = {a0.x, a0.y, a0.z, a0.w, a1.x, a1.y, a1.z, a1.w};
            float br[8] = {b0.x, b0.y, b0.z, b0.w, b1.x, b1.y, b1.z, b1.w};
#pragma unroll
            for (int i = 0; i < 8; i++)
#pragma unroll
                for (int j = 0; j < 8; j++) acc[i][j] += ar[i] * br[j];
        }
        __syncthreads();
    }
    float sqn[8], sqm[8];
#pragma unroll
    for (int i = 0; i < 8; i++) {
        sqn[i] = g_sq[b * NN + n0 + (i >> 2) * 64 + ty * 4 + (i & 3)];
        sqm[i] = g_sq[b * NN + m0 + (i >> 2) * 64 + tx * 4 + (i & 3)];
    }
    float vals[8][8];
#pragma unroll
    for (int i = 0; i < 8; i++)
#pragma unroll
        for (int j = 0; j < 8; j++)
            vals[i][j] = 2.f * acc[i][j] - sqn[i] - sqm[j];

    float* base = g_pair + (size_t)b * NN * NN;
    // normal tile: rows n, coalesced float4
#pragma unroll
    for (int i = 0; i < 8; i++) {
        int n = n0 + (i >> 2) * 64 + ty * 4 + (i & 3);
        float* dst = base + (size_t)n * NN + m0;
        *(float4*)&dst[tx * 4]      = make_float4(vals[i][0], vals[i][1], vals[i][2], vals[i][3]);
        *(float4*)&dst[64 + tx * 4] = make_float4(vals[i][4], vals[i][5], vals[i][6], vals[i][7]);
    }
    // mirror tile (off-diagonal only): rows m, float4 along n
    if (tn != tm) {
#pragma unroll
        for (int j = 0; j < 8; j++) {
            int m = m0 + (j >> 2) * 64 + tx * 4 + (j & 3);
            float* dst = base + (size_t)m * NN + n0;
            *(float4*)&dst[ty * 4]      = make_float4(vals[0][j], vals[1][j], vals[2][j], vals[3][j]);
            *(float4*)&dst[64 + ty * 4] = make_float4(vals[4][j], vals[5][j], vals[6][j], vals[7][j]);
        }
    }
}

// ---------------- top-K: warp per row; lane-local sorted top-20, then 20 warp-argmax rounds ----------------
__global__ __launch_bounds__(256) void k_topk() {
    __shared__ float sv[8][32][21];
    __shared__ int   si[8][32][21];
    int warp = threadIdx.x >> 5, lane = threadIdx.x & 31;
    int r = blockIdx.x * 8 + warp;
    int b = r >> 10, n = r & 1023;
    const float* row = g_pair + (size_t)b * NN * NN + (size_t)n * NN;

    float* v = sv[warp][lane];
    int* ii = si[warp][lane];
#pragma unroll
    for (int t = 0; t < KK; t++) { v[t] = -FLT_MAX; ii[t] = 1 << 30; }

    for (int j = lane; j < NN; j += 32) {
        float p = row[j];
        if (p > v[KK - 1]) {                       // strict: equal keeps earlier (lower) index
            int pos = KK - 1;
            while (pos > 0 && v[pos - 1] < p) {    // strict: stable among ties
                v[pos] = v[pos - 1]; ii[pos] = ii[pos - 1]; pos--;
            }
            v[pos] = p; ii[pos] = j;
        }
    }
    __syncwarp();

    int ptr = 0;
    for (int t = 0; t < KK; t++) {
        float hv = (ptr < KK) ? v[ptr] : -FLT_MAX;
        int   hi = (ptr < KK) ? ii[ptr] : (1 << 30);
        float bv = hv; int bi = hi;
#pragma unroll
        for (int off = 16; off; off >>= 1) {
            float ov = __shfl_xor_sync(0xffffffffu, bv, off);
            int   oi = __shfl_xor_sync(0xffffffffu, bi, off);
            if (ov > bv || (ov == bv && oi < bi)) { bv = ov; bi = oi; }
        }
        if (hi == bi) ptr++;                       // winner lane (indices unique) advances
        if (lane == 0) g_idx[r * KK + t] = bi;
    }
}

// ---------------- SGEMM 128x128x8, 8x8/thread: g_ad = X @ g_wta  (M=BN, N=Nw, K=C) ----------------
__global__ __launch_bounds__(256) void k_gemm(const float* ext, int ldx, int coff, int C, int Nw) {
    __shared__ float As[8][132];   // As[k][m]
    __shared__ float Bs[8][132];   // Bs[k][n]
    const float* X = src_ptr(ext, coff);
    int n0 = blockIdx.x * 128;
    int m0 = blockIdx.y * 128;
    int tid = threadIdx.x;
    int tx = tid & 15, ty = tid >> 4;
    int arow = tid >> 1, akq = (tid & 1) * 4;
    int bk = tid >> 5, bn4 = (tid & 31) * 4;

    float acc[8][8];
#pragma unroll
    for (int i = 0; i < 8; i++)
#pragma unroll
        for (int j = 0; j < 8; j++) acc[i][j] = 0.f;

    for (int c0 = 0; c0 < C; c0 += 8) {
        // A: X rows m0..m0+127, k = c0..c0+7; transpose into As[k][row]
        float4 xv = make_float4(0.f, 0.f, 0.f, 0.f);
        const float* Xr = X + (size_t)(m0 + arow) * ldx + c0 + akq;
        if (c0 + akq + 3 < C) {
            xv = *(const float4*)Xr;
        } else {
            if (c0 + akq + 0 < C) xv.x = Xr[0];
            if (c0 + akq + 1 < C) xv.y = Xr[1];
            if (c0 + akq + 2 < C) xv.z = Xr[2];
        }
        As[akq + 0][arow] = xv.x;
        As[akq + 1][arow] = xv.y;
        As[akq + 2][arow] = xv.z;
        As[akq + 3][arow] = xv.w;
        // B: weights (C x Nw)
        float4 wv = make_float4(0.f, 0.f, 0.f, 0.f);
        if (c0 + bk < C) wv = *(const float4*)&g_wta[(size_t)(c0 + bk) * Nw + n0 + bn4];
        *(float4*)&Bs[bk][bn4] = wv;
        __syncthreads();
#pragma unroll
        for (int k = 0; k < 8; k++) {
            float4 a0 = *(const float4*)&As[k][ty * 4];
            float4 a1 = *(const float4*)&As[k][64 + ty * 4];
            float4 b0 = *(const float4*)&Bs[k][tx * 4];
            float4 b1 = *(const float4*)&Bs[k][64 + tx * 4];
            float ar[8] = {a0.x, a0.y, a0.z, a0.w, a1.x, a1.y, a1.z, a1.w};
            float br[8] = {b0.x, b0.y, b0.z, b0.w, b1.x, b1.y, b1.z, b1.w};
#pragma unroll
            for (int i = 0; i < 8; i++)
#pragma unroll
                for (int j = 0; j < 8; j++) acc[i][j] += ar[i] * br[j];
        }
        __syncthreads();
    }
#pragma unroll
    for (int i = 0; i < 8; i++) {
        int m = m0 + (i >> 2) * 64 + ty * 4 + (i & 3);
        float* dst = g_ad + (size_t)m * Nw + n0;
        *(float4*)&dst[tx * 4]      = make_float4(acc[i][0], acc[i][1], acc[i][2], acc[i][3]);
        *(float4*)&dst[64 + tx * 4] = make_float4(acc[i][4], acc[i][5], acc[i][6], acc[i][7]);
    }
}

// ---------------- gather + per-(b,n) max/min over k + partial channel sums ----------------
__global__ void k_gather(int O, int Ow) {
    int r = blockIdx.x;
    int b = r >> 10;
    __shared__ int sidx[KK];
    if (threadIdx.x < KK) sidx[threadIdx.x] = g_idx[r * KK + threadIdx.x];
    __syncthreads();
    int o = threadIdx.x;
    float dv = g_ad[(size_t)r * Ow + O + o];
    float ymx = -FLT_MAX, ymn = FLT_MAX, s1 = 0.f, s2 = 0.f;
#pragma unroll
    for (int k = 0; k < KK; k++) {
        float y = g_ad[(size_t)(b * NN + sidx[k]) * Ow + o] + dv;
        ymx = fmaxf(ymx, y);
        ymn = fminf(ymn, y);
        s1 += y;
        s2 += y * y;
    }
    g_ymax[(size_t)r * O + o] = ymx;
    g_ymin[(size_t)r * O + o] = ymn;
    g_ps1[(size_t)r * O + o] = s1;
    g_ps2[(size_t)r * O + o] = s2;
}

// ---------------- deterministic channel-stat reduction (2 levels) ----------------
__global__ void k_stat1(int O) {
    int ox = threadIdx.x & 31;
    int wy = threadIdx.x >> 5;
    int o = blockIdx.x * 32 + ox;
    int ci = blockIdx.y;
    const int CH = BN / 16;
    float s1 = 0.f, s2 = 0.f;
    int r0 = ci * CH;
    for (int r = r0 + wy; r < r0 + CH; r += 8) {
        s1 += g_ps1[(size_t)r * O + o];
        s2 += g_ps2[(size_t)r * O + o];
    }
    __shared__ float sh1[8][32], sh2[8][32];
    sh1[wy][ox] = s1; sh2[wy][ox] = s2;
    __syncthreads();
    if (wy == 0) {
        for (int w = 1; w < 8; w++) { s1 += sh1[w][ox]; s2 += sh2[w][ox]; }
        g_cs1[ci * O + o] = s1;
        g_cs2[ci * O + o] = s2;
    }
}

__global__ void k_stat2(int O, const float* __restrict__ g, const float* __restrict__ be, float invcnt) {
    int o = blockIdx.x * 256 + threadIdx.x;
    if (o >= O) return;
    float s1 = 0.f, s2 = 0.f;
    for (int ci = 0; ci < 16; ci++) { s1 += g_cs1[ci * O + o]; s2 += g_cs2[ci * O + o]; }
    float m = s1 * invcnt;
    float v = s2 * invcnt - m * m;
    float sc = g[o] * rsqrtf(v + EPSV);
    g_stats[o * 3 + 0] = m;
    g_stats[o * 3 + 1] = sc;
    g_stats[o * 3 + 2] = be[o];
}

// ---------------- finalize a block: pick max/min by sign(scale), BN affine, lrelu ----------------
__global__ void k_final(int O, int coff) {
    int r = blockIdx.x;
    int o = threadIdx.x;
    float m = g_stats[o * 3 + 0];
    float sc = g_stats[o * 3 + 1];
    float be = g_stats[o * 3 + 2];
    float y = (sc >= 0.f) ? g_ymax[(size_t)r * O + o] : g_ymin[(size_t)r * O + o];
    float t = (y - m) * sc + be;
    g_cat[(size_t)r * 512 + coff + o] = (t >= 0.f) ? t : 0.2f * t;
}

// ---------------- final stage: per-(b,o) max/min over N + channel sums ----------------
__global__ void k_fred() {
    int ox = threadIdx.x & 31;
    int wy = threadIdx.x >> 5;
    int o = blockIdx.x * 32 + ox;
    int b = blockIdx.y;
    float mx = -FLT_MAX, mn = FLT_MAX, s1 = 0.f, s2 = 0.f;
    for (int n = wy; n < NN; n += 8) {
        float v = g_ad[(size_t)(b * NN + n) * 512 + o];
        mx = fmaxf(mx, v);
        mn = fminf(mn, v);
        s1 += v;
        s2 += v * v;
    }
    __shared__ float smx[8][32], smn[8][32], ss1[8][32], ss2[8][32];
    smx[wy][ox] = mx; smn[wy][ox] = mn; ss1[wy][ox] = s1; ss2[wy][ox] = s2;
    __syncthreads();
    if (wy == 0) {
        for (int w = 1; w < 8; w++) {
            mx = fmaxf(mx, smx[w][ox]);
            mn = fminf(mn, smn[w][ox]);
            s1 += ss1[w][ox];
            s2 += ss2[w][ox];
        }
        g_bmax[b * 512 + o] = mx;
        g_bmin[b * 512 + o] = mn;
        g_bs1[b * 512 + o] = s1;
        g_bs2[b * 512 + o] = s2;
    }
}

__global__ void k_feat(const float* __restrict__ g5, const float* __restrict__ b5) {
    int o = blockIdx.x * 256 + threadIdx.x;
    if (o >= 512) return;
    float s1 = 0.f, s2 = 0.f;
    for (int b = 0; b < BB; b++) { s1 += g_bs1[b * 512 + o]; s2 += g_bs2[b * 512 + o]; }
    float m = s1 / 8192.f;
    float v = s2 / 8192.f - m * m;
    float sc = g5[o] * rsqrtf(v + EPSV);
    float be = b5[o];
    for (int b = 0; b < BB; b++) {
        float y = (sc >= 0.f) ? g_bmax[b * 512 + o] : g_bmin[b * 512 + o];
        float t = (y - m) * sc + be;
        g_feat[b * 512 + o] = (t >= 0.f) ? t : 0.2f * t;
    }
}

__global__ void k_out(const float* __restrict__ wemb, float* __restrict__ out) {
    int b = blockIdx.x;
    int f = threadIdx.x;  // 256
    __shared__ float fr[512];
    for (int i = threadIdx.x; i < 512; i += 256) fr[i] = g_feat[b * 512 + i];
    __syncthreads();
    float acc = 0.f;
    for (int o = 0; o < 512; o++) acc += fr[o] * wemb[f * 512 + o];
    out[b * 256 + f] = acc;
}

// ---------------- host orchestration ----------------
static void run_stage(const float* xext, int ldx, int coff, int C, int O,
                      const float* w, const float* g, const float* bb, int outcoff) {
    int Nw = 2 * O;
    k_prep_w<<<(C * O + 255) / 256, 256>>>(w, C, O, 1);
    k_xt<<<(BB * C * NN + 255) / 256, 256>>>(xext, ldx, coff, C);
    k_sq<<<BN / 256, 256>>>(xext, ldx, coff, C);
    k_pair<<<dim3(36, 1, BB), 256>>>(C);
    k_topk<<<BN / 8, 256>>>();
    k_gemm<<<dim3(Nw / 128, BN / 128), 256>>>(xext, ldx, coff, C, Nw);
    k_gather<<<BN, O>>>(O, Nw);
    k_stat1<<<dim3(O / 32, 16), 256>>>(O);
    k_stat2<<<(O + 255) / 256, 256>>>(O, g, bb, 1.0f / (float)(BN * KK));
    k_final<<<BN, O>>>(O, outcoff);
}

extern "C" void kernel_launch(void* const* d_in, const int* in_sizes, int n_in,
                              void* d_out, int out_size) {
    const float* x    = (const float*)d_in[0];
    const float* w1   = (const float*)d_in[1];
    const float* g1   = (const float*)d_in[2];
    const float* b1   = (const float*)d_in[3];
    const float* w2   = (const float*)d_in[4];
    const float* g2   = (const float*)d_in[5];
    const float* b2   = (const float*)d_in[6];
    const float* w3   = (const float*)d_in[7];
    const float* g3   = (const float*)d_in[8];
    const float* b3   = (const float*)d_in[9];
    const float* w4   = (const float*)d_in[10];
    const float* g4   = (const float*)d_in[11];
    const float* b4   = (const float*)d_in[12];
    const float* w5   = (const float*)d_in[13];
    const float* g5   = (const float*)d_in[14];
    const float* b5   = (const float*)d_in[15];
    const float* wemb = (const float*)d_in[16];
    float* out = (float*)d_out;

    // edge blocks: input (ptr, ld, coff, C) -> output channels at outcoff in g_cat
    run_stage(x,       3,   0,   3,   64, w1, g1, b1,   0);
    run_stage(nullptr, 512, 0,   64,  64, w2, g2, b2,  64);
    run_stage(nullptr, 512, 64,  64, 128, w3, g3, b3, 128);
    run_stage(nullptr, 512, 128, 128, 256, w4, g4, b4, 256);

    // final: y5 = cat @ w5^T  (512x512), stats over (b,n), per-b max over n, lrelu, @ wemb^T
    k_prep_w<<<(512 * 512 + 255) / 256, 256>>>(w5, 512, 512, 0);
    k_gemm<<<dim3(512 / 128, BN / 128), 256>>>(nullptr, 512, 0, 512, 512);
    k_fred<<<dim3(512 / 32, BB), 256>>>();
    k_feat<<<2, 256>>>(g5, b5);
    k_out<<<BB, 256>>>(wemb, out);
}